// round 16
// baseline (speedup 1.0000x reference)
#include <cuda_runtime.h>

#define NROWS   131072
#define DIM     640
#define NSRC    32
#define HID     256
#define CCHUNK  128
#define NCC     (DIM / CCHUNK)       // 5
#define NPAIR   (NCC * NSRC)         // 160
#define UJB     44                   // j-blocks per pair (one per warp)
#define UNITS   (NPAIR * UJB)        // 7040
#define NCHUNK  512                  // label chunks of 256
#define NBLK    444                  // 3 CTAs/SM x 148 SMs: exact single wave

// ---- Scratch (__device__ globals) ----
__device__ unsigned char g_lab8[NROWS];
__device__ int   g_cnt_part[NCHUNK][NSRC];
__device__ int   g_reg_part[NCHUNK];
__device__ int   g_seg_start[NSRC];
__device__ int   g_seg_cnt[NSRC];
__device__ int   g_rowidx[NROWS];
__device__ float g_p2[NPAIR][UJB][CCHUNK];     // 3.6 MB partials (L2-resident)
// software grid barrier: count self-resets; gen monotonic (replay-safe)
__device__ unsigned int g_bar_count;
__device__ unsigned int g_bar_gen;

__device__ __forceinline__ void grid_barrier(unsigned int bar_base, int i) {
    __syncthreads();
    if (threadIdx.x == 0) {
        __threadfence();
        const unsigned int n = atomicAdd(&g_bar_count, 1u);
        if (n == NBLK - 1) {
            atomicExch(&g_bar_count, 0u);
            __threadfence();
            atomicAdd(&g_bar_gen, 1u);
        }
        while ((int)(*(volatile unsigned int*)&g_bar_gen - bar_base) < i) { }
        __threadfence();
    }
    __syncthreads();
}

// ---------------------------------------------------------------------------
// K0 (fused): labels+counts -> bar -> regularity AND -> [generic: prefix +
// scatter -> bar] -> streaming segment sums. 444 CTAs x 512, single wave.
// (Identical to the R13 kernel that measured 58.1 us.)
// ---------------------------------------------------------------------------
__global__ void __launch_bounds__(512, 3)
fused_seg_kernel(const float* __restrict__ x, const int* __restrict__ lab32) {
    const int t = threadIdx.x, b = blockIdx.x;
    const int lane = t & 31, w = t >> 5;
    unsigned int bar_base = 0;
    if (t == 0) bar_base = *(volatile unsigned int*)&g_bar_gen;

    __shared__ int cntA[NSRC], cntB[NSRC];
    __shared__ int okAB[2];
    __shared__ int stot[NSRC], sstart[NSRC];
    const int hasB = (b + NBLK < NCHUNK);

    if (t < NSRC) { cntA[t] = 0; cntB[t] = 0; }
    if (t < 2) okAB[t] = 1;
    __syncthreads();

    // labels[1]==1 in-dataset => second int32 word is 0 iff 8-byte labels
    const int is64 = (lab32[1] == 0) ? 1 : 0;
    int lidx = -1, lab = 0;
    if (t < 256) lidx = b * 256 + t;
    else if (hasB) lidx = (b + NBLK) * 256 + (t - 256);
    if (lidx >= 0) {
        lab = lab32[(size_t)lidx << is64];
        g_lab8[lidx] = (unsigned char)lab;
        if (lab != (lidx & 31)) atomicExch(&okAB[t >> 8], 0);
        atomicAdd((t < 256) ? &cntA[lab] : &cntB[lab], 1);
    }
    __syncthreads();
    if (t < NSRC) g_cnt_part[b][t] = cntA[t];
    if (hasB && t >= 32 && t < 64) g_cnt_part[b + NBLK][t - 32] = cntB[t - 32];
    if (t == 0) g_reg_part[b] = okAB[0];
    if (t == 1 && hasB) g_reg_part[b + NBLK] = okAB[1];

    grid_barrier(bar_base, 1);

    const int regular = __syncthreads_and(g_reg_part[t]);   // NCHUNK==512==blockDim

    if (regular) {
        if (b == 0 && t < NSRC) {
            g_seg_cnt[t] = NROWS / NSRC;
            g_seg_start[t] = t * (NROWS / NSRC);
        }
    } else {
        // ======== generic path (cold) ========
        __shared__ int s16[16][NSRC];
        {
            const int l = t >> 4, g = t & 15;
            int p = 0;
            for (int c = g * 32; c < g * 32 + 32; ++c) p += g_cnt_part[c][l];
            s16[g][l] = p;
        }
        __syncthreads();
        if (t < NSRC) {
            int tot = 0;
            #pragma unroll
            for (int g = 0; g < 16; ++g) tot += s16[g][t];
            stot[t] = tot;
            int inc = tot;
            #pragma unroll
            for (int o = 1; o < 32; o <<= 1) {
                int n = __shfl_up_sync(0xffffffffu, inc, o);
                if (t >= o) inc += n;
            }
            sstart[t] = inc - tot;
            if (b == 0) { g_seg_cnt[t] = tot; g_seg_start[t] = inc - tot; }
        }
        __syncthreads();
        __shared__ int baseA[NSRC], baseB[NSRC];
        if (t < NSRC) {
            int r = sstart[t];
            for (int c = 0; c < b; ++c) r += g_cnt_part[c][t];
            baseA[t] = r;
        } else if (t >= 32 && t < 64 && hasB) {
            const int l = t - 32;
            int r = sstart[l];
            for (int c = 0; c < b + NBLK; ++c) r += g_cnt_part[c][l];
            baseB[l] = r;
        }
        __shared__ int cw[16][NSRC];
        cw[w][lane] = 0;
        __syncthreads();
        int riw = 0;
        if (lidx >= 0) {
            const unsigned mask = __match_any_sync(0xffffffffu, lab);
            riw = __popc(mask & ((1u << lane) - 1u));
            if (riw == 0) cw[w][lab] = __popc(mask);
        }
        __syncthreads();
        if (lidx >= 0) {
            const int w0 = (w < 8) ? 0 : 8;
            int off = 0;
            for (int wp = w0; wp < w; ++wp) off += cw[wp][lab];
            const int base = (w < 8) ? baseA[lab] : baseB[lab];
            g_rowidx[base + off + riw] = lidx;
        }
        grid_barrier(bar_base, 2);
    }

    // ---- streaming segment sums ----
    const int W = b * 16 + w;
    if (W >= UNITS) return;
    const int pair = W / UJB;
    const int jb   = W - pair * UJB;
    const int cc   = pair >> 5, s = pair & 31;
    const float* __restrict__ xb = x + cc * CCHUNK + lane * 4;
    float4 acc = make_float4(0.f, 0.f, 0.f, 0.f);

    if (regular) {
        const int nj = (NROWS / NSRC + UJB - 1) / UJB;      // 94
        const int j0 = jb * nj;
        const int j1 = min(NROWS / NSRC, j0 + nj);
        #pragma unroll 8
        for (int j = j0; j < j1; ++j) {
            const size_t r = (size_t)j * NSRC + s;
            const float4 v = *reinterpret_cast<const float4*>(xb + r * DIM);
            acc.x += v.x; acc.y += v.y; acc.z += v.z; acc.w += v.w;
        }
    } else {
        const int cnt = stot[s];
        const int nj = (cnt + UJB - 1) / UJB;
        const int j0 = jb * nj;
        const int j1 = min(cnt, j0 + nj);
        const int* __restrict__ ridx = g_rowidx + sstart[s];
        for (int jbb = j0; jbb < j1; jbb += 32) {
            const int lim = min(32, j1 - jbb);
            int myidx = (lane < lim) ? ridx[jbb + lane] : 0;
            for (int it = 0; it < lim; ++it) {
                const int r = __shfl_sync(0xffffffffu, myidx, it);
                const float4 v = *reinterpret_cast<const float4*>(xb + (size_t)r * DIM);
                acc.x += v.x; acc.y += v.y; acc.z += v.z; acc.w += v.w;
            }
        }
    }
    *reinterpret_cast<float4*>(&g_p2[pair][jb][lane * 4]) = acc;
}

// ---------------------------------------------------------------------------
// K1: per-segment full tail — reduce -> mean -> h -> logits -> softmax -> out.
// Grid 32 (block = segment s), 512 threads. Row s of the output depends only
// on segment s, so there is NO cross-block dependency and NO third kernel.
// ---------------------------------------------------------------------------
__global__ void __launch_bounds__(512)
mlp_row_kernel(const float* __restrict__ W1, const float* __restrict__ b1,
               const float* __restrict__ W2, const float* __restrict__ b2,
               float* __restrict__ out, int out_size) {
    const int s = blockIdx.x, t = threadIdx.x;
    __shared__ float mean[DIM];
    __shared__ float w1p[2][HID];
    __shared__ float hsh[HID];

    const float inv = 1.0f / (float)g_seg_cnt[s];

    // reduce g_p2 (L2-resident) -> mean. cols t and t+512; 44 jb each,
    // coalesced 512B rows, unrolled for MLP.
    #pragma unroll
    for (int base = 0; base < DIM; base += 512) {
        const int c = base + t;
        if (c < DIM) {
            const int cc = c >> 7, col = c & 127;
            const int pair = cc * NSRC + s;
            float sum = 0.f;
            #pragma unroll 11
            for (int jb = 0; jb < UJB; ++jb) sum += g_p2[pair][jb][col];
            mean[c] = sum * inv;
        }
    }
    __syncthreads();

    // h = relu(mean @ W1 + b1): thread (hh = t&255, dh = t>>8) covers 320 d's
    // with 8-register W1 prefetch chunks; W1 row-major [DIM][HID].
    {
        const int hh = t & 255, dh = t >> 8;
        const float* __restrict__ w1 = W1 + (size_t)(dh * 320) * HID + hh;
        const float* __restrict__ mm = &mean[dh * 320];
        float a0 = 0.f, a1 = 0.f, a2 = 0.f, a3 = 0.f;
        #pragma unroll 5
        for (int dc = 0; dc < 320; dc += 8) {
            float wr[8];
            #pragma unroll
            for (int i = 0; i < 8; ++i) wr[i] = w1[(size_t)(dc + i) * HID];
            a0 = fmaf(mm[dc + 0], wr[0], a0); a1 = fmaf(mm[dc + 1], wr[1], a1);
            a2 = fmaf(mm[dc + 2], wr[2], a2); a3 = fmaf(mm[dc + 3], wr[3], a3);
            a0 = fmaf(mm[dc + 4], wr[4], a0); a1 = fmaf(mm[dc + 5], wr[5], a1);
            a2 = fmaf(mm[dc + 6], wr[6], a2); a3 = fmaf(mm[dc + 7], wr[7], a3);
        }
        w1p[dh][hh] = (a0 + a1) + (a2 + a3);
    }
    __syncthreads();
    if (t < HID)
        hsh[t] = fmaxf(w1p[0][t] + w1p[1][t] + b1[t], 0.f);
    __syncthreads();

    // logits + softmax on warp 0: lane = output column, 256-iter dot with
    // smem-broadcast h and coalesced W2 rows (row-major [HID][NSRC]).
    if (t < 32) {
        float acc = b2[t];
        #pragma unroll 8
        for (int k = 0; k < HID; ++k)
            acc = fmaf(hsh[k], W2[k * NSRC + t], acc);

        float mx = acc;
        #pragma unroll
        for (int o = 16; o > 0; o >>= 1)
            mx = fmaxf(mx, __shfl_xor_sync(0xffffffffu, mx, o));
        const float e = expf(acc - mx);
        float sum = e;
        #pragma unroll
        for (int o = 16; o > 0; o >>= 1)
            sum += __shfl_xor_sync(0xffffffffu, sum, o);

        out[s * NSRC + t] = e / sum;
        if (s == 0 && out_size >= NSRC * NSRC + NSRC)
            out[NSRC * NSRC + t] = (float)t;
    }
}

// ---------------------------------------------------------------------------
extern "C" void kernel_launch(void* const* d_in, const int* in_sizes, int n_in,
                              void* d_out, int out_size) {
    const float* x   = (const float*)d_in[0];
    const int*   lab = (const int*)d_in[1];
    const float* W1  = (const float*)d_in[2];
    const float* b1  = (const float*)d_in[3];
    const float* W2  = (const float*)d_in[4];
    const float* b2  = (const float*)d_in[5];
    float* out = (float*)d_out;

    fused_seg_kernel<<<NBLK, 512>>>(x, lab);
    mlp_row_kernel<<<NSRC, 512>>>(W1, b1, W2, b2, out, out_size);
}

// round 17
// speedup vs baseline: 1.4260x; 1.4260x over previous
#include <cuda_runtime.h>

#define NROWS   131072
#define DIM     640
#define NSRC    32
#define HID     256
#define CCHUNK  128
#define NCC     (DIM / CCHUNK)       // 5
#define NPAIR   (NCC * NSRC)         // 160
#define UJB     44                   // j-blocks per pair (one per warp)
#define UNITS   (NPAIR * UJB)        // 7040
#define KC2     20                   // mlp1 k-chunks of 32 cols
#define NCHUNK  512                  // label chunks of 256
#define NBLK    444                  // 3 CTAs/SM x 148 SMs: exact single wave

// ---- Scratch (__device__ globals) ----
__device__ unsigned char g_lab8[NROWS];
__device__ int   g_cnt_part[NCHUNK][NSRC];
__device__ int   g_reg_part[NCHUNK];
__device__ int   g_seg_start[NSRC];
__device__ int   g_seg_cnt[NSRC];
__device__ int   g_rowidx[NROWS];
__device__ float g_p2[NPAIR][UJB][CCHUNK];     // 3.6 MB partials (L2-resident)
__device__ float g_h1p[KC2][NSRC][HID];
// software grid barrier: count self-resets; gen monotonic (replay-safe)
__device__ unsigned int g_bar_count;
__device__ unsigned int g_bar_gen;

__device__ __forceinline__ void grid_barrier(unsigned int bar_base, int i) {
    __syncthreads();
    if (threadIdx.x == 0) {
        __threadfence();
        const unsigned int n = atomicAdd(&g_bar_count, 1u);
        if (n == NBLK - 1) {
            atomicExch(&g_bar_count, 0u);
            __threadfence();
            atomicAdd(&g_bar_gen, 1u);
        }
        while ((int)(*(volatile unsigned int*)&g_bar_gen - bar_base) < i) { }
        __threadfence();
    }
    __syncthreads();
}

// ---------------------------------------------------------------------------
// K0 (fused): labels+counts -> bar -> regularity AND -> [generic: prefix +
// scatter -> bar] -> streaming segment sums. 444 CTAs x 512, single wave.
// (Byte-identical to the R13 kernel.)
// ---------------------------------------------------------------------------
__global__ void __launch_bounds__(512, 3)
fused_seg_kernel(const float* __restrict__ x, const int* __restrict__ lab32) {
    const int t = threadIdx.x, b = blockIdx.x;
    const int lane = t & 31, w = t >> 5;
    unsigned int bar_base = 0;
    if (t == 0) bar_base = *(volatile unsigned int*)&g_bar_gen;

    __shared__ int cntA[NSRC], cntB[NSRC];
    __shared__ int okAB[2];
    __shared__ int stot[NSRC], sstart[NSRC];
    const int hasB = (b + NBLK < NCHUNK);

    if (t < NSRC) { cntA[t] = 0; cntB[t] = 0; }
    if (t < 2) okAB[t] = 1;
    __syncthreads();

    // labels[1]==1 in-dataset => second int32 word is 0 iff 8-byte labels
    const int is64 = (lab32[1] == 0) ? 1 : 0;
    int lidx = -1, lab = 0;
    if (t < 256) lidx = b * 256 + t;
    else if (hasB) lidx = (b + NBLK) * 256 + (t - 256);
    if (lidx >= 0) {
        lab = lab32[(size_t)lidx << is64];
        g_lab8[lidx] = (unsigned char)lab;
        if (lab != (lidx & 31)) atomicExch(&okAB[t >> 8], 0);
        atomicAdd((t < 256) ? &cntA[lab] : &cntB[lab], 1);
    }
    __syncthreads();
    if (t < NSRC) g_cnt_part[b][t] = cntA[t];
    if (hasB && t >= 32 && t < 64) g_cnt_part[b + NBLK][t - 32] = cntB[t - 32];
    if (t == 0) g_reg_part[b] = okAB[0];
    if (t == 1 && hasB) g_reg_part[b + NBLK] = okAB[1];

    grid_barrier(bar_base, 1);

    const int regular = __syncthreads_and(g_reg_part[t]);   // NCHUNK==512==blockDim

    if (regular) {
        if (b == 0 && t < NSRC) {
            g_seg_cnt[t] = NROWS / NSRC;
            g_seg_start[t] = t * (NROWS / NSRC);
        }
    } else {
        // ======== generic path (cold) ========
        __shared__ int s16[16][NSRC];
        {
            const int l = t >> 4, g = t & 15;
            int p = 0;
            for (int c = g * 32; c < g * 32 + 32; ++c) p += g_cnt_part[c][l];
            s16[g][l] = p;
        }
        __syncthreads();
        if (t < NSRC) {
            int tot = 0;
            #pragma unroll
            for (int g = 0; g < 16; ++g) tot += s16[g][t];
            stot[t] = tot;
            int inc = tot;
            #pragma unroll
            for (int o = 1; o < 32; o <<= 1) {
                int n = __shfl_up_sync(0xffffffffu, inc, o);
                if (t >= o) inc += n;
            }
            sstart[t] = inc - tot;
            if (b == 0) { g_seg_cnt[t] = tot; g_seg_start[t] = inc - tot; }
        }
        __syncthreads();
        __shared__ int baseA[NSRC], baseB[NSRC];
        if (t < NSRC) {
            int r = sstart[t];
            for (int c = 0; c < b; ++c) r += g_cnt_part[c][t];
            baseA[t] = r;
        } else if (t >= 32 && t < 64 && hasB) {
            const int l = t - 32;
            int r = sstart[l];
            for (int c = 0; c < b + NBLK; ++c) r += g_cnt_part[c][l];
            baseB[l] = r;
        }
        __shared__ int cw[16][NSRC];
        cw[w][lane] = 0;
        __syncthreads();
        int riw = 0;
        if (lidx >= 0) {
            const unsigned mask = __match_any_sync(0xffffffffu, lab);
            riw = __popc(mask & ((1u << lane) - 1u));
            if (riw == 0) cw[w][lab] = __popc(mask);
        }
        __syncthreads();
        if (lidx >= 0) {
            const int w0 = (w < 8) ? 0 : 8;
            int off = 0;
            for (int wp = w0; wp < w; ++wp) off += cw[wp][lab];
            const int base = (w < 8) ? baseA[lab] : baseB[lab];
            g_rowidx[base + off + riw] = lidx;
        }
        grid_barrier(bar_base, 2);
    }

    // ---- streaming segment sums ----
    const int W = b * 16 + w;
    if (W >= UNITS) return;
    const int pair = W / UJB;
    const int jb   = W - pair * UJB;
    const int cc   = pair >> 5, s = pair & 31;
    const float* __restrict__ xb = x + cc * CCHUNK + lane * 4;
    float4 acc = make_float4(0.f, 0.f, 0.f, 0.f);

    if (regular) {
        const int nj = (NROWS / NSRC + UJB - 1) / UJB;      // 94
        const int j0 = jb * nj;
        const int j1 = min(NROWS / NSRC, j0 + nj);
        #pragma unroll 8
        for (int j = j0; j < j1; ++j) {
            const size_t r = (size_t)j * NSRC + s;
            const float4 v = *reinterpret_cast<const float4*>(xb + r * DIM);
            acc.x += v.x; acc.y += v.y; acc.z += v.z; acc.w += v.w;
        }
    } else {
        const int cnt = stot[s];
        const int nj = (cnt + UJB - 1) / UJB;
        const int j0 = jb * nj;
        const int j1 = min(cnt, j0 + nj);
        const int* __restrict__ ridx = g_rowidx + sstart[s];
        for (int jbb = j0; jbb < j1; jbb += 32) {
            const int lim = min(32, j1 - jbb);
            int myidx = (lane < lim) ? ridx[jbb + lane] : 0;
            for (int it = 0; it < lim; ++it) {
                const int r = __shfl_sync(0xffffffffu, myidx, it);
                const float4 v = *reinterpret_cast<const float4*>(xb + (size_t)r * DIM);
                acc.x += v.x; acc.y += v.y; acc.z += v.z; acc.w += v.w;
            }
        }
    }
    *reinterpret_cast<float4*>(&g_p2[pair][jb][lane * 4]) = acc;
}

// ---------------------------------------------------------------------------
// K1: reduce g_p2 -> mean + mlp1 partial. Grid (32 s, 20 kc) = 640 blocks,
// 512 thr. Per-thread W1 dot = 16 d's = 2 prefetch epochs, issued BEFORE the
// reduce so their latency overlaps it. 10240 warps chip-wide.
// ---------------------------------------------------------------------------
__global__ void __launch_bounds__(512)
mlp1_kernel(const float* __restrict__ W1) {
    const int s = blockIdx.x, kc = blockIdx.y;
    const int t = threadIdx.x;
    const int cc = kc >> 2, off = (kc & 3) * 32;
    const int pair = cc * NSRC + s;
    __shared__ float sred[UJB][32];
    __shared__ float m[32];
    __shared__ float w1p[2][HID];

    // W1 prefetch: thread (hh = t&255, dh = t>>8) covers d = kc*32+dh*16 ..+16
    const int hh = t & 255, dh = t >> 8;
    const float* __restrict__ w1 = W1 + (size_t)(kc * 32 + dh * 16) * HID + hh;
    float wr[16];
    #pragma unroll
    for (int i = 0; i < 16; ++i) wr[i] = w1[(size_t)i * HID];

    // g_p2 reduce: 352 threads, one float4 each (jb = t>>3, 16B col slice)
    if (t < UJB * 8) {
        const int jb = t >> 3, c4 = (t & 7) * 4;
        *reinterpret_cast<float4*>(&sred[jb][c4]) =
            *reinterpret_cast<const float4*>(&g_p2[pair][jb][off + c4]);
    }
    __syncthreads();
    if (t < 32) {
        float sum = 0.f;
        #pragma unroll
        for (int jb = 0; jb < UJB; ++jb) sum += sred[jb][t];
        m[t] = sum / (float)g_seg_cnt[s];
    }
    __syncthreads();

    // FMA: smem-broadcast m x register-resident W1
    {
        const float* __restrict__ mm = &m[dh * 16];
        float a0 = 0.f, a1 = 0.f, a2 = 0.f, a3 = 0.f;
        #pragma unroll
        for (int i = 0; i < 16; i += 4) {
            a0 = fmaf(mm[i + 0], wr[i + 0], a0);
            a1 = fmaf(mm[i + 1], wr[i + 1], a1);
            a2 = fmaf(mm[i + 2], wr[i + 2], a2);
            a3 = fmaf(mm[i + 3], wr[i + 3], a3);
        }
        w1p[dh][hh] = (a0 + a1) + (a2 + a3);
    }
    __syncthreads();
    if (t < 256) g_h1p[kc][s][t] = w1p[0][t] + w1p[1][t];
}

// ---------------------------------------------------------------------------
// K2: finalize h + logits + softmax + output. 1 CTA x 1024, 64 KB dyn smem.
// ---------------------------------------------------------------------------
extern __shared__ float s_dyn[];
__global__ void __launch_bounds__(1024)
mlp2_kernel(const float* __restrict__ W2, const float* __restrict__ b1,
            const float* __restrict__ b2,
            float* __restrict__ out, int out_size) {
    float* h   = s_dyn;                 // [NSRC][HID]
    float* w2s = s_dyn + NSRC * HID;    // [HID][NSRC]
    const int tid = threadIdx.x;

    #pragma unroll
    for (int i = tid; i < NSRC * HID; i += 1024) {
        const int s = i >> 8, hh = i & 255;
        float a = b1[hh];
        #pragma unroll
        for (int kcc = 0; kcc < KC2; ++kcc) a += g_h1p[kcc][s][hh];
        h[i] = fmaxf(a, 0.f);
    }
    #pragma unroll
    for (int i = tid; i < HID * NSRC; i += 1024) w2s[i] = W2[i];
    __syncthreads();

    const int t = tid & 31, s = tid >> 5;
    float acc = b2[t];
    const float* hrow = &h[s * HID];
    #pragma unroll 8
    for (int k = 0; k < HID; ++k)
        acc = fmaf(hrow[k], w2s[k * NSRC + t], acc);

    float mx = acc;
    #pragma unroll
    for (int o = 16; o > 0; o >>= 1)
        mx = fmaxf(mx, __shfl_xor_sync(0xffffffffu, mx, o));
    const float e = expf(acc - mx);
    float sum = e;
    #pragma unroll
    for (int o = 16; o > 0; o >>= 1)
        sum += __shfl_xor_sync(0xffffffffu, sum, o);

    out[s * NSRC + t] = e / sum;
    if (tid < NSRC && out_size >= NSRC * NSRC + NSRC)
        out[NSRC * NSRC + tid] = (float)tid;
}

// ---------------------------------------------------------------------------
extern "C" void kernel_launch(void* const* d_in, const int* in_sizes, int n_in,
                              void* d_out, int out_size) {
    const float* x   = (const float*)d_in[0];
    const int*   lab = (const int*)d_in[1];
    const float* W1  = (const float*)d_in[2];
    const float* b1  = (const float*)d_in[3];
    const float* W2  = (const float*)d_in[4];
    const float* b2  = (const float*)d_in[5];
    float* out = (float*)d_out;

    const int smem2 = (NSRC * HID + HID * NSRC) * (int)sizeof(float);  // 64 KB
    static int smem_set = 0;
    if (!smem_set) {
        cudaFuncSetAttribute(mlp2_kernel,
                             cudaFuncAttributeMaxDynamicSharedMemorySize, smem2);
        smem_set = 1;
    }

    fused_seg_kernel<<<NBLK, 512>>>(x, lab);
    mlp1_kernel<<<dim3(NSRC, KC2), 512>>>(W1);
    mlp2_kernel<<<1, 1024, smem2>>>(W2, b1, b2, out, out_size);
}